// round 1
// baseline (speedup 1.0000x reference)
#include <cuda_runtime.h>

// ---------------------------------------------------------------------------
// Problem constants
// ---------------------------------------------------------------------------
#define HH   56
#define WWID 56
#define DDEP 28
#define LTOK 87808          // 56*56*28
#define CDIM 96
#define NWIN 256            // 8*8*4 windows
#define NTOK 343            // 7*7*7 tokens per window
#define NHEAD 3
#define HDIM 32
#define FF   384

// ---------------------------------------------------------------------------
// Scratch (device globals; no allocation allowed)
// ---------------------------------------------------------------------------
__device__ __align__(16) float g_H  [(size_t)LTOK * CDIM];   // LN1 + shift + window-partitioned
__device__ __align__(16) float g_QKV[(size_t)LTOK * 288];    // qkv output (window order)
__device__ __align__(16) float g_O  [(size_t)LTOK * CDIM];   // attention output (window order)
__device__ __align__(16) float g_X  [(size_t)LTOK * CDIM];   // shortcut + proj (token order)
__device__ __align__(16) float g_X2 [(size_t)LTOK * CDIM];   // LN2 output
__device__ __align__(16) float g_FF [(size_t)LTOK * FF];     // fc1+gelu output
__device__ int g_DST[LTOK];                                  // window-row -> token index map

// ---------------------------------------------------------------------------
// Packed f32x2 helpers (sm_103a: FFMA2 only reachable via PTX fma.rn.f32x2)
// ---------------------------------------------------------------------------
__device__ __forceinline__ unsigned long long pk2(float x, float y) {
    unsigned long long r;
    asm("mov.b64 %0, {%1, %2};" : "=l"(r) : "f"(x), "f"(y));
    return r;
}
__device__ __forceinline__ void upk2(unsigned long long v, float& x, float& y) {
    asm("mov.b64 {%0, %1}, %2;" : "=f"(x), "=f"(y) : "l"(v));
}
__device__ __forceinline__ void fma2(unsigned long long& d, unsigned long long a, unsigned long long b) {
    asm("fma.rn.f32x2 %0, %1, %2, %0;" : "+l"(d) : "l"(a), "l"(b));
}
__device__ __forceinline__ void mul2(unsigned long long& d, unsigned long long c) {
    asm("mul.rn.f32x2 %0, %0, %1;" : "+l"(d) : "l"(c));
}

// ---------------------------------------------------------------------------
// LayerNorm (one warp per token).
// PERM=true : gather with cyclic shift + window partition, record inverse map.
// PERM=false: plain LN over g_X -> g_X2.
// ---------------------------------------------------------------------------
template <bool PERM>
__global__ void __launch_bounds__(256) ln_kernel(const float* __restrict__ in,
                                                 const float* __restrict__ gamma,
                                                 const float* __restrict__ beta)
{
    int gw   = (blockIdx.x * 256 + threadIdx.x) >> 5;   // token (row) index
    int lane = threadIdx.x & 31;
    if (gw >= LTOK) return;

    const float* inp;
    float* outp;
    if (PERM) {
        int w = gw / NTOK, n = gw - w * NTOK;
        int iH = w >> 5, iW = (w >> 2) & 7, iD = w & 3;
        int a = n / 49; int r = n - a * 49; int b = r / 7; int c = r - b * 7;
        int th = iH * 7 + a + 3; if (th >= HH)   th -= HH;
        int tw = iW * 7 + b + 3; if (tw >= WWID) tw -= WWID;
        int td = iD * 7 + c + 3; if (td >= DDEP) td -= DDEP;
        int src = (th * WWID + tw) * DDEP + td;
        if (lane == 0) g_DST[gw] = src;
        inp  = in + (size_t)src * CDIM;
        outp = g_H + (size_t)gw * CDIM;
    } else {
        inp  = g_X + (size_t)gw * CDIM;
        outp = g_X2 + (size_t)gw * CDIM;
    }

    float v0 = inp[lane], v1 = inp[lane + 32], v2 = inp[lane + 64];
    float s  = v0 + v1 + v2;
    float ss = fmaf(v0, v0, fmaf(v1, v1, v2 * v2));
#pragma unroll
    for (int o = 16; o; o >>= 1) {
        s  += __shfl_xor_sync(0xffffffffu, s, o);
        ss += __shfl_xor_sync(0xffffffffu, ss, o);
    }
    float mean = s * (1.0f / 96.0f);
    float var  = ss * (1.0f / 96.0f) - mean * mean;
    float inv  = rsqrtf(var + 1e-5f);
    outp[lane]      = (v0 - mean) * inv * gamma[lane]      + beta[lane];
    outp[lane + 32] = (v1 - mean) * inv * gamma[lane + 32] + beta[lane + 32];
    outp[lane + 64] = (v2 - mean) * inv * gamma[lane + 64] + beta[lane + 64];
}

// ---------------------------------------------------------------------------
// Generic fp32 GEMM, C[M,N] = A[M,K] @ B[K,N] (+ per-mode epilogue).
// Tile 128x48, KC=32, 256 threads, micro-tile 8 rows x 3 cols, f32x2 packed.
// MODE 0: qkv  (A=g_H,  out=g_QKV, scale q cols by 32^-0.5)
// MODE 1: proj (A=g_O,  scatter out to g_X via g_DST, + residual x)
// MODE 2: fc1  (A=g_X2, out=g_FF, exact GELU)
// MODE 3: fc2  (A=g_FF, out=d_out, + residual g_X)
// ---------------------------------------------------------------------------
#define BM 128
#define BN 48
#define KC 32
#define APAD 136   // As row stride (floats)
#define BPAD 52    // Bs row stride (floats)

template <int MODE>
__device__ __forceinline__ void epi_store(int m, int n, float v,
                                          const float* __restrict__ res,
                                          float* __restrict__ outp)
{
    if (MODE == 0) {
        if (n < 96) v *= 0.17677669529663689f;   // 32^-0.5 on q
        g_QKV[(size_t)m * 288 + n] = v;
    } else if (MODE == 1) {
        int d = g_DST[m];
        g_X[(size_t)d * CDIM + n] = res[(size_t)d * CDIM + n] + v;
    } else if (MODE == 2) {
        g_FF[(size_t)m * FF + n] = 0.5f * v * (1.0f + erff(v * 0.70710678118654752f));
    } else {
        outp[(size_t)m * CDIM + n] = v + g_X[(size_t)m * CDIM + n];
    }
}

template <int MODE>
__global__ void __launch_bounds__(256) gemm_kernel(const float* __restrict__ Bw,
                                                   const float* __restrict__ bias,
                                                   const float* __restrict__ res,
                                                   float* __restrict__ outp,
                                                   int K, int Ntot)
{
    __shared__ __align__(16) float As[KC * APAD];
    __shared__ __align__(16) float Bs[KC * BPAD];

    const float* A;
    if      (MODE == 0) A = g_H;
    else if (MODE == 1) A = g_O;
    else if (MODE == 2) A = g_X2;
    else                A = g_FF;

    int m0  = blockIdx.y * BM;
    int n0  = blockIdx.x * BN;
    int tid = threadIdx.x;
    int rg  = tid >> 4;     // 0..15 (8 rows each)
    int cg  = tid & 15;     // 0..15 (3 cols each)

    unsigned long long acc[4][3];
#pragma unroll
    for (int i = 0; i < 4; i++)
#pragma unroll
        for (int j = 0; j < 3; j++) acc[i][j] = 0ull;

    for (int k0 = 0; k0 < K; k0 += KC) {
        // A tile: 128 rows x 32 k, transposed into As[k][m]
#pragma unroll
        for (int i = 0; i < 4; i++) {
            int idx = tid + 256 * i;
            int m = idx >> 3, q = idx & 7;
            float4 v = *reinterpret_cast<const float4*>(A + (size_t)(m0 + m) * K + (k0 + q * 4));
            int kl = q * 4;
            As[(kl + 0) * APAD + m] = v.x;
            As[(kl + 1) * APAD + m] = v.y;
            As[(kl + 2) * APAD + m] = v.z;
            As[(kl + 3) * APAD + m] = v.w;
        }
        // B tile: 32 x 48
#pragma unroll
        for (int i = 0; i < 6; i++) {
            int idx = tid + 256 * i;
            int kk = idx / 48, nn = idx - kk * 48;
            Bs[kk * BPAD + nn] = Bw[(size_t)(k0 + kk) * Ntot + n0 + nn];
        }
        __syncthreads();

#pragma unroll
        for (int k = 0; k < KC; k++) {
            const ulonglong2* ap = reinterpret_cast<const ulonglong2*>(&As[k * APAD + rg * 8]);
            ulonglong2 a01 = ap[0];
            ulonglong2 a23 = ap[1];
            float b0 = Bs[k * BPAD + cg * 3 + 0];
            float b1 = Bs[k * BPAD + cg * 3 + 1];
            float b2 = Bs[k * BPAD + cg * 3 + 2];
            unsigned long long B0 = pk2(b0, b0), B1 = pk2(b1, b1), B2 = pk2(b2, b2);
            fma2(acc[0][0], a01.x, B0); fma2(acc[0][1], a01.x, B1); fma2(acc[0][2], a01.x, B2);
            fma2(acc[1][0], a01.y, B0); fma2(acc[1][1], a01.y, B1); fma2(acc[1][2], a01.y, B2);
            fma2(acc[2][0], a23.x, B0); fma2(acc[2][1], a23.x, B1); fma2(acc[2][2], a23.x, B2);
            fma2(acc[3][0], a23.y, B0); fma2(acc[3][1], a23.y, B1); fma2(acc[3][2], a23.y, B2);
        }
        __syncthreads();
    }

#pragma unroll
    for (int c = 0; c < 3; c++) {
        int n = n0 + cg * 3 + c;
        float bv = bias[n];
#pragma unroll
        for (int rp = 0; rp < 4; rp++) {
            float lo, hi;
            upk2(acc[rp][c], lo, hi);
            int m = m0 + rg * 8 + rp * 2;
            epi_store<MODE>(m,     n, lo + bv, res, outp);
            epi_store<MODE>(m + 1, n, hi + bv, res, outp);
        }
    }
}

// ---------------------------------------------------------------------------
// Windowed attention: one block per (window, head). 352 threads (343 queries).
// K, V, per-head bias table, and (rel-idx, mask-region) metadata in smem.
// Online softmax, everything packed f32x2.
// ---------------------------------------------------------------------------
__global__ void __launch_bounds__(352) attn_kernel(const float* __restrict__ rpb)
{
    extern __shared__ __align__(16) float sm[];
    float* Ksm = sm;                   // 343*32
    float* Vsm = sm + 10976;           // 343*32
    float* Bsm = sm + 21952;           // 2197
    int*   Msm = (int*)(sm + 24149);   // 343

    int w   = blockIdx.x / 3;
    int h   = blockIdx.x - w * 3;
    int tid = threadIdx.x;
    const float* base = g_QKV + (size_t)w * NTOK * 288;

    for (int i = tid; i < NTOK * 32; i += 352) {
        int n = i >> 5, j = i & 31;
        Ksm[i] = base[n * 288 + 96  + h * 32 + j];
        Vsm[i] = base[n * 288 + 192 + h * 32 + j];
    }
    for (int i = tid; i < 2197; i += 352)
        Bsm[i] = rpb[i * 3 + h];

    int iH = w >> 5, iW = (w >> 2) & 7, iD = w & 3;
    int sh0 = iH * 7, sw0 = iW * 7, sd0 = iD * 7;
    for (int m = tid; m < NTOK; m += 352) {
        int a = m / 49; int r = m - a * 49; int b = r / 7; int c = r - b * 7;
        int sub = a * 169 + b * 13 + c;
        int ph = sh0 + a, pw = sw0 + b, pd = sd0 + c;
        int rh = (ph < 49) ? 0 : ((ph < 53) ? 1 : 2);
        int rw = (pw < 49) ? 0 : ((pw < 53) ? 1 : 2);
        int rd = (pd < 21) ? 0 : ((pd < 25) ? 1 : 2);
        Msm[m] = sub | (((rh * 3 + rw) * 3 + rd) << 16);
    }
    __syncthreads();

    if (tid >= NTOK) return;
    int n = tid;

    unsigned long long q[16];
    {
        const ulonglong2* qp = reinterpret_cast<const ulonglong2*>(base + n * 288 + h * 32);
#pragma unroll
        for (int i = 0; i < 8; i++) { ulonglong2 t = qp[i]; q[2 * i] = t.x; q[2 * i + 1] = t.y; }
    }
    int metan = Msm[n];
    int ibase = (metan & 0xffff) + 1098;   // (+6)*169 + (+6)*13 + (+6)
    int cntn  = metan >> 16;

    unsigned long long o[16];
#pragma unroll
    for (int i = 0; i < 16; i++) o[i] = 0ull;
    float mo = -1e30f, l = 0.0f;

    for (int m = 0; m < NTOK; m++) {
        const ulonglong2* kp = reinterpret_cast<const ulonglong2*>(Ksm + m * 32);
        unsigned long long s0 = 0, s1 = 0, s2 = 0, s3 = 0;
#pragma unroll
        for (int i = 0; i < 4; i++) {
            ulonglong2 ka = kp[2 * i], kb = kp[2 * i + 1];
            fma2(s0, q[4 * i + 0], ka.x);
            fma2(s1, q[4 * i + 1], ka.y);
            fma2(s2, q[4 * i + 2], kb.x);
            fma2(s3, q[4 * i + 3], kb.y);
        }
        float x0, x1, x2, x3, x4, x5, x6, x7;
        upk2(s0, x0, x1); upk2(s1, x2, x3); upk2(s2, x4, x5); upk2(s3, x6, x7);
        float s = ((x0 + x1) + (x2 + x3)) + ((x4 + x5) + (x6 + x7));

        int mm = Msm[m];
        s += Bsm[ibase - (mm & 0xffff)];
        if (cntn != (mm >> 16)) s -= 100.0f;

        if (s > mo) {
            float corr = __expf(mo - s);
            l *= corr;
            unsigned long long c2 = pk2(corr, corr);
#pragma unroll
            for (int i = 0; i < 16; i++) mul2(o[i], c2);
            mo = s;
        }
        float p = __expf(s - mo);
        l += p;
        unsigned long long p2 = pk2(p, p);
        const ulonglong2* vp = reinterpret_cast<const ulonglong2*>(Vsm + m * 32);
#pragma unroll
        for (int i = 0; i < 8; i++) {
            ulonglong2 va = vp[i];
            fma2(o[2 * i],     p2, va.x);
            fma2(o[2 * i + 1], p2, va.y);
        }
    }

    float inv = 1.0f / l;
    float* op = g_O + ((size_t)w * NTOK + n) * CDIM + h * 32;
#pragma unroll
    for (int i = 0; i < 16; i++) {
        float lo, hi; upk2(o[i], lo, hi);
        float2 st; st.x = lo * inv; st.y = hi * inv;
        *reinterpret_cast<float2*>(op + 2 * i) = st;
    }
}

// ---------------------------------------------------------------------------
// Launch
// ---------------------------------------------------------------------------
extern "C" void kernel_launch(void* const* d_in, const int* in_sizes, int n_in,
                              void* d_out, int out_size)
{
    const float* x      = (const float*)d_in[0];
    const float* n1g    = (const float*)d_in[1];
    const float* n1b    = (const float*)d_in[2];
    const float* qkv_w  = (const float*)d_in[3];
    const float* qkv_b  = (const float*)d_in[4];
    const float* rpb    = (const float*)d_in[5];
    const float* proj_w = (const float*)d_in[6];
    const float* proj_b = (const float*)d_in[7];
    const float* n2g    = (const float*)d_in[8];
    const float* n2b    = (const float*)d_in[9];
    const float* fc1_w  = (const float*)d_in[10];
    const float* fc1_b  = (const float*)d_in[11];
    const float* fc2_w  = (const float*)d_in[12];
    const float* fc2_b  = (const float*)d_in[13];
    float* out = (float*)d_out;

    const int attn_smem = (10976 * 2 + 2197) * 4 + 343 * 4;   // 97968 B
    cudaFuncSetAttribute(attn_kernel, cudaFuncAttributeMaxDynamicSharedMemorySize, 98304);

    ln_kernel<true><<<LTOK / 8, 256>>>(x, n1g, n1b);

    dim3 gq(288 / BN, LTOK / BM);
    gemm_kernel<0><<<gq, 256>>>(qkv_w, qkv_b, nullptr, nullptr, 96, 288);

    attn_kernel<<<NWIN * NHEAD, 352, attn_smem>>>(rpb);

    dim3 gp(96 / BN, LTOK / BM);
    gemm_kernel<1><<<gp, 256>>>(proj_w, proj_b, x, nullptr, 96, 96);

    ln_kernel<false><<<LTOK / 8, 256>>>(x, n2g, n2b);

    dim3 g1(FF / BN, LTOK / BM);
    gemm_kernel<2><<<g1, 256>>>(fc1_w, fc1_b, nullptr, nullptr, 96, FF);

    dim3 g2(96 / BN, LTOK / BM);
    gemm_kernel<3><<<g2, 256>>>(fc2_w, fc2_b, nullptr, out, FF, 96);
}

// round 3
// speedup vs baseline: 1.3637x; 1.3637x over previous
#include <cuda_runtime.h>
#include <cstdint>

// ---------------------------------------------------------------------------
// Problem constants
// ---------------------------------------------------------------------------
#define HH   56
#define WWID 56
#define DDEP 28
#define LTOK 87808          // 56*56*28
#define CDIM 96
#define NWIN 256
#define NTOK 343
#define NHEAD 3
#define FF   384
#define BN   96             // GEMM N tile
#define BM   128            // GEMM M tile
#define KC   32             // GEMM K chunk
#define KPAD 36             // smem row stride (floats)

// ---------------------------------------------------------------------------
// Scratch (device globals; no allocation allowed)
// ---------------------------------------------------------------------------
__device__ __align__(16) float g_H  [(size_t)LTOK * CDIM];
__device__ __align__(16) float g_QKV[(size_t)LTOK * 288];
__device__ __align__(16) float g_O  [(size_t)LTOK * CDIM];
__device__ __align__(16) float g_X  [(size_t)LTOK * CDIM];
__device__ __align__(16) float g_X2 [(size_t)LTOK * CDIM];
__device__ __align__(16) float g_FF [(size_t)LTOK * FF];
__device__ int g_DST[LTOK];
// pre-transposed weights [N,K]
__device__ __align__(16) float g_WtQKV [288 * 96];
__device__ __align__(16) float g_WtPROJ[96 * 96];
__device__ __align__(16) float g_WtFC1 [384 * 96];
__device__ __align__(16) float g_WtFC2 [96 * 384];

// ---------------------------------------------------------------------------
// f32x2 packed helpers (attention)
// ---------------------------------------------------------------------------
__device__ __forceinline__ unsigned long long pk2(float x, float y) {
    unsigned long long r;
    asm("mov.b64 %0, {%1, %2};" : "=l"(r) : "f"(x), "f"(y));
    return r;
}
__device__ __forceinline__ void upk2(unsigned long long v, float& x, float& y) {
    asm("mov.b64 {%0, %1}, %2;" : "=f"(x), "=f"(y) : "l"(v));
}
__device__ __forceinline__ void fma2(unsigned long long& d, unsigned long long a, unsigned long long b) {
    asm("fma.rn.f32x2 %0, %1, %2, %0;" : "+l"(d) : "l"(a), "l"(b));
}
__device__ __forceinline__ void mul2(unsigned long long& d, unsigned long long c) {
    asm("mul.rn.f32x2 %0, %0, %1;" : "+l"(d) : "l"(c));
}
__device__ __forceinline__ void add2(unsigned long long& d, unsigned long long s) {
    asm("add.rn.f32x2 %0, %0, %1;" : "+l"(d) : "l"(s));
}

__device__ __forceinline__ uint32_t f2tf32(float x) {
    uint32_t u;
    asm("cvt.rna.tf32.f32 %0, %1;" : "=r"(u) : "f"(x));
    return u;
}
__device__ __forceinline__ void mma8(float* c, const uint32_t* a, uint32_t b0, uint32_t b1) {
    asm("mma.sync.aligned.m16n8k8.row.col.f32.tf32.tf32.f32 "
        "{%0,%1,%2,%3}, {%4,%5,%6,%7}, {%8,%9}, {%0,%1,%2,%3};"
        : "+f"(c[0]), "+f"(c[1]), "+f"(c[2]), "+f"(c[3])
        : "r"(a[0]), "r"(a[1]), "r"(a[2]), "r"(a[3]), "r"(b0), "r"(b1));
}

// ---------------------------------------------------------------------------
// LayerNorm (one warp per token)
// ---------------------------------------------------------------------------
template <bool PERM>
__global__ void __launch_bounds__(256) ln_kernel(const float* __restrict__ in,
                                                 const float* __restrict__ gamma,
                                                 const float* __restrict__ beta)
{
    int gw   = (blockIdx.x * 256 + threadIdx.x) >> 5;
    int lane = threadIdx.x & 31;
    if (gw >= LTOK) return;

    const float* inp;
    float* outp;
    if (PERM) {
        int w = gw / NTOK, n = gw - w * NTOK;
        int iH = w >> 5, iW = (w >> 2) & 7, iD = w & 3;
        int a = n / 49; int r = n - a * 49; int b = r / 7; int c = r - b * 7;
        int th = iH * 7 + a + 3; if (th >= HH)   th -= HH;
        int tw = iW * 7 + b + 3; if (tw >= WWID) tw -= WWID;
        int td = iD * 7 + c + 3; if (td >= DDEP) td -= DDEP;
        int src = (th * WWID + tw) * DDEP + td;
        if (lane == 0) g_DST[gw] = src;
        inp  = in + (size_t)src * CDIM;
        outp = g_H + (size_t)gw * CDIM;
    } else {
        inp  = g_X + (size_t)gw * CDIM;
        outp = g_X2 + (size_t)gw * CDIM;
    }

    float v0 = inp[lane], v1 = inp[lane + 32], v2 = inp[lane + 64];
    float s  = v0 + v1 + v2;
    float ss = fmaf(v0, v0, fmaf(v1, v1, v2 * v2));
#pragma unroll
    for (int o = 16; o; o >>= 1) {
        s  += __shfl_xor_sync(0xffffffffu, s, o);
        ss += __shfl_xor_sync(0xffffffffu, ss, o);
    }
    float mean = s * (1.0f / 96.0f);
    float var  = ss * (1.0f / 96.0f) - mean * mean;
    float inv  = rsqrtf(var + 1e-5f);
    outp[lane]      = (v0 - mean) * inv * gamma[lane]      + beta[lane];
    outp[lane + 32] = (v1 - mean) * inv * gamma[lane + 32] + beta[lane + 32];
    outp[lane + 64] = (v2 - mean) * inv * gamma[lane + 64] + beta[lane + 64];
}

// ---------------------------------------------------------------------------
// Weight transpose W[K,N] -> Wt[N,K]  (Wt selected by MODE, device globals)
// ---------------------------------------------------------------------------
template <int MODE>
__global__ void transpose_w(const float* __restrict__ W, int K, int N)
{
    float* Wt = (MODE == 0) ? g_WtQKV : (MODE == 1) ? g_WtPROJ
              : (MODE == 2) ? g_WtFC1 : g_WtFC2;
    int idx = blockIdx.x * 256 + threadIdx.x;
    if (idx < K * N) {
        int k = idx / N, n = idx - k * N;
        Wt[n * K + k] = W[idx];
    }
}

// ---------------------------------------------------------------------------
// mma.sync tf32 GEMM: C[128,96] = A[128,K] @ Wt[96,K]^T (+ epilogue)
// 256 threads = 8 warps (4 row x 2 col). Warp tile 32x48 = 2x6 m16n8k8.
// MODE 0: qkv (q-scale on n-block 0)  MODE 1: proj (scatter+residual)
// MODE 2: fc1 (GELU)                  MODE 3: fc2 (+residual -> d_out)
// ---------------------------------------------------------------------------
#define GEMM_SMEM 49664   // max(epilogue 128*97*4, As 128*36*4 + Bs 96*36*4)

template <int MODE>
__global__ void __launch_bounds__(256) gemm_mma(const float* __restrict__ bias,
                                                const float* __restrict__ res,
                                                float* __restrict__ outp,
                                                int K)
{
    extern __shared__ __align__(16) char smraw[];
    uint32_t* Asu = (uint32_t*)smraw;                 // [128][36]
    uint32_t* Bsu = (uint32_t*)(smraw + 18432);       // [96][36]
    float*    Sf  = (float*)smraw;                    // epilogue [128][97]

    const float* A  = (MODE == 0) ? g_H : (MODE == 1) ? g_O : (MODE == 2) ? g_X2 : g_FF;
    const float* Wt = (MODE == 0) ? g_WtQKV : (MODE == 1) ? g_WtPROJ
                    : (MODE == 2) ? g_WtFC1 : g_WtFC2;

    int tid  = threadIdx.x;
    int wid  = tid >> 5, lane = tid & 31;
    int wr   = wid >> 1, wc = wid & 1;       // warp grid 4x2
    int g    = lane >> 2, c = lane & 3;      // fragment coords
    int m0   = blockIdx.y * BM;
    int n0   = blockIdx.x * BN;

    float acc[2][6][4];
#pragma unroll
    for (int t = 0; t < 2; t++)
#pragma unroll
        for (int u = 0; u < 6; u++)
#pragma unroll
            for (int j = 0; j < 4; j++) acc[t][u][j] = 0.0f;

    int nc = K >> 5;
    for (int ch = 0; ch < nc; ch++) {
        int k0 = ch << 5;
        __syncthreads();
        // stage A chunk: 128 x 32, tf32-rounded
#pragma unroll
        for (int i = 0; i < 4; i++) {
            int idx = tid + (i << 8);
            int row = idx >> 3, q = idx & 7;
            float4 v = *(const float4*)(A + (size_t)(m0 + row) * K + k0 + (q << 2));
            uint4 u4; u4.x = f2tf32(v.x); u4.y = f2tf32(v.y); u4.z = f2tf32(v.z); u4.w = f2tf32(v.w);
            *(uint4*)(Asu + row * KPAD + (q << 2)) = u4;
        }
        // stage B chunk: 96 x 32
#pragma unroll
        for (int i = 0; i < 3; i++) {
            int idx = tid + (i << 8);
            int row = idx >> 3, q = idx & 7;
            float4 v = *(const float4*)(Wt + (size_t)(n0 + row) * K + k0 + (q << 2));
            uint4 u4; u4.x = f2tf32(v.x); u4.y = f2tf32(v.y); u4.z = f2tf32(v.z); u4.w = f2tf32(v.w);
            *(uint4*)(Bsu + row * KPAD + (q << 2)) = u4;
        }
        __syncthreads();

#pragma unroll
        for (int ks = 0; ks < 4; ks++) {
            int kk = (ks << 3) + c;
            uint32_t a[2][4];
#pragma unroll
            for (int t = 0; t < 2; t++) {
                int r0 = wr * 32 + t * 16 + g;
                a[t][0] = Asu[r0 * KPAD + kk];
                a[t][1] = Asu[(r0 + 8) * KPAD + kk];
                a[t][2] = Asu[r0 * KPAD + kk + 4];
                a[t][3] = Asu[(r0 + 8) * KPAD + kk + 4];
            }
#pragma unroll
            for (int u = 0; u < 6; u++) {
                int nb = wc * 48 + u * 8 + g;
                uint32_t b0 = Bsu[nb * KPAD + kk];
                uint32_t b1 = Bsu[nb * KPAD + kk + 4];
                mma8(acc[0][u], a[0], b0, b1);
                mma8(acc[1][u], a[1], b0, b1);
            }
        }
    }
    __syncthreads();

    // Epilogue: registers -> staged smem [128][97] with bias/scale/GELU
#pragma unroll
    for (int t = 0; t < 2; t++) {
#pragma unroll
        for (int u = 0; u < 6; u++) {
            int r0 = wr * 32 + t * 16 + g;
            int nn = wc * 48 + u * 8 + 2 * c;
            float b0 = __ldg(bias + n0 + nn);
            float b1 = __ldg(bias + n0 + nn + 1);
            float v0 = acc[t][u][0] + b0, v1 = acc[t][u][1] + b1;
            float v2 = acc[t][u][2] + b0, v3 = acc[t][u][3] + b1;
            if (MODE == 0 && n0 == 0) {
                v0 *= 0.17677669529663689f; v1 *= 0.17677669529663689f;
                v2 *= 0.17677669529663689f; v3 *= 0.17677669529663689f;
            }
            if (MODE == 2) {
                v0 = 0.5f * v0 * (1.0f + erff(v0 * 0.70710678118654752f));
                v1 = 0.5f * v1 * (1.0f + erff(v1 * 0.70710678118654752f));
                v2 = 0.5f * v2 * (1.0f + erff(v2 * 0.70710678118654752f));
                v3 = 0.5f * v3 * (1.0f + erff(v3 * 0.70710678118654752f));
            }
            Sf[r0 * 97 + nn] = v0;       Sf[r0 * 97 + nn + 1] = v1;
            Sf[(r0 + 8) * 97 + nn] = v2; Sf[(r0 + 8) * 97 + nn + 1] = v3;
        }
    }
    __syncthreads();

    // Coalesced float4 stores (+ residual / scatter)
#pragma unroll
    for (int i = 0; i < 12; i++) {
        int idx = tid + (i << 8);
        int row = idx / 24, q4 = idx - row * 24;
        int m = m0 + row, n = n0 + (q4 << 2);
        const float* sp = Sf + row * 97 + (q4 << 2);
        float4 v; v.x = sp[0]; v.y = sp[1]; v.z = sp[2]; v.w = sp[3];
        if (MODE == 0) {
            *(float4*)(g_QKV + (size_t)m * 288 + n) = v;
        } else if (MODE == 1) {
            int d0 = g_DST[m];
            float4 r = *(const float4*)(res + (size_t)d0 * 96 + n);
            v.x += r.x; v.y += r.y; v.z += r.z; v.w += r.w;
            *(float4*)(g_X + (size_t)d0 * 96 + n) = v;
        } else if (MODE == 2) {
            *(float4*)(g_FF + (size_t)m * 384 + n) = v;
        } else {
            float4 r = *(const float4*)(g_X + (size_t)m * 96 + n);
            v.x += r.x; v.y += r.y; v.z += r.z; v.w += r.w;
            *(float4*)(outp + (size_t)m * 96 + n) = v;
        }
    }
}

// ---------------------------------------------------------------------------
// Windowed attention: block = (window, head); 704 threads, 2 threads/query
// (head-dim halves, paired via shfl_xor 1). Online softmax, f32x2.
// ---------------------------------------------------------------------------
__global__ void __launch_bounds__(704, 1) attn_kernel(const float* __restrict__ rpb)
{
    extern __shared__ __align__(16) float sm[];
    float* Ksm = sm;                   // 343*32
    float* Vsm = sm + 10976;           // 343*32
    float* Bsm = sm + 21952;           // 2197
    int*   Msm = (int*)(sm + 24149);   // 343

    int w   = blockIdx.x / 3;
    int h   = blockIdx.x - w * 3;
    int tid = threadIdx.x;
    const float* base = g_QKV + (size_t)w * NTOK * 288;

    for (int i = tid; i < NTOK * 32; i += 704) {
        int n = i >> 5, j = i & 31;
        Ksm[i] = base[n * 288 + 96  + h * 32 + j];
        Vsm[i] = base[n * 288 + 192 + h * 32 + j];
    }
    for (int i = tid; i < 2197; i += 704)
        Bsm[i] = rpb[i * 3 + h];

    int iH = w >> 5, iW = (w >> 2) & 7, iD = w & 3;
    for (int m = tid; m < NTOK; m += 704) {
        int a = m / 49; int r = m - a * 49; int b = r / 7; int c = r - b * 7;
        int sub = a * 169 + b * 13 + c;
        int ph = iH * 7 + a, pw = iW * 7 + b, pd = iD * 7 + c;
        int rh = (ph < 49) ? 0 : ((ph < 53) ? 1 : 2);
        int rw = (pw < 49) ? 0 : ((pw < 53) ? 1 : 2);
        int rd = (pd < 21) ? 0 : ((pd < 25) ? 1 : 2);
        Msm[m] = sub | (((rh * 3 + rw) * 3 + rd) << 16);
    }
    __syncthreads();

    int n = tid >> 1; if (n > 342) n = 342;
    int half = tid & 1;
    bool valid = (tid < 686);

    unsigned long long q[8];
    {
        const ulonglong2* qp = (const ulonglong2*)(base + n * 288 + h * 32 + half * 16);
#pragma unroll
        for (int i = 0; i < 4; i++) { ulonglong2 t = qp[i]; q[2 * i] = t.x; q[2 * i + 1] = t.y; }
    }
    int metan = Msm[n];
    int ibase = (metan & 0xffff) + 1098;
    int cntn  = metan >> 16;

    unsigned long long o[8];
#pragma unroll
    for (int i = 0; i < 8; i++) o[i] = 0ull;
    float mo = -1e30f, l = 0.0f;

    for (int m = 0; m < NTOK; m++) {
        const ulonglong2* kp = (const ulonglong2*)(Ksm + m * 32 + half * 16);
        unsigned long long s0 = 0, s1 = 0, s2 = 0, s3 = 0;
        ulonglong2 ka = kp[0], kb = kp[1];
        fma2(s0, q[0], ka.x); fma2(s1, q[1], ka.y);
        fma2(s2, q[2], kb.x); fma2(s3, q[3], kb.y);
        ulonglong2 kc = kp[2], kd = kp[3];
        fma2(s0, q[4], kc.x); fma2(s1, q[5], kc.y);
        fma2(s2, q[6], kd.x); fma2(s3, q[7], kd.y);
        add2(s0, s1); add2(s2, s3); add2(s0, s2);
        float xa, xb; upk2(s0, xa, xb);
        float part = xa + xb;
        float s = part + __shfl_xor_sync(0xffffffffu, part, 1);

        int mm = Msm[m];
        s += Bsm[ibase - (mm & 0xffff)];
        if (cntn != (mm >> 16)) s -= 100.0f;

        if (s > mo) {
            float corr = __expf(mo - s);
            l *= corr;
            unsigned long long c2 = pk2(corr, corr);
#pragma unroll
            for (int i = 0; i < 8; i++) mul2(o[i], c2);
            mo = s;
        }
        float p = __expf(s - mo);
        l += p;
        unsigned long long p2 = pk2(p, p);
        const ulonglong2* vp = (const ulonglong2*)(Vsm + m * 32 + half * 16);
#pragma unroll
        for (int i = 0; i < 4; i++) {
            ulonglong2 va = vp[i];
            fma2(o[2 * i],     p2, va.x);
            fma2(o[2 * i + 1], p2, va.y);
        }
    }

    if (valid) {
        float inv = 1.0f / l;
        float* op = g_O + ((size_t)w * NTOK + n) * CDIM + h * 32 + half * 16;
#pragma unroll
        for (int i = 0; i < 8; i++) {
            float lo, hi; upk2(o[i], lo, hi);
            float2 st; st.x = lo * inv; st.y = hi * inv;
            *(float2*)(op + 2 * i) = st;
        }
    }
}

// ---------------------------------------------------------------------------
// Launch
// ---------------------------------------------------------------------------
extern "C" void kernel_launch(void* const* d_in, const int* in_sizes, int n_in,
                              void* d_out, int out_size)
{
    const float* x      = (const float*)d_in[0];
    const float* n1g    = (const float*)d_in[1];
    const float* n1b    = (const float*)d_in[2];
    const float* qkv_w  = (const float*)d_in[3];
    const float* qkv_b  = (const float*)d_in[4];
    const float* rpb    = (const float*)d_in[5];
    const float* proj_w = (const float*)d_in[6];
    const float* proj_b = (const float*)d_in[7];
    const float* n2g    = (const float*)d_in[8];
    const float* n2b    = (const float*)d_in[9];
    const float* fc1_w  = (const float*)d_in[10];
    const float* fc1_b  = (const float*)d_in[11];
    const float* fc2_w  = (const float*)d_in[12];
    const float* fc2_b  = (const float*)d_in[13];
    float* out = (float*)d_out;

    cudaFuncSetAttribute(gemm_mma<0>, cudaFuncAttributeMaxDynamicSharedMemorySize, GEMM_SMEM);
    cudaFuncSetAttribute(gemm_mma<1>, cudaFuncAttributeMaxDynamicSharedMemorySize, GEMM_SMEM);
    cudaFuncSetAttribute(gemm_mma<2>, cudaFuncAttributeMaxDynamicSharedMemorySize, GEMM_SMEM);
    cudaFuncSetAttribute(gemm_mma<3>, cudaFuncAttributeMaxDynamicSharedMemorySize, GEMM_SMEM);
    cudaFuncSetAttribute(attn_kernel, cudaFuncAttributeMaxDynamicSharedMemorySize, 98304);

    const int attn_smem = (10976 * 2 + 2197) * 4 + 343 * 4;

    transpose_w<0><<<(96 * 288 + 255) / 256, 256>>>(qkv_w,  96, 288);
    transpose_w<1><<<(96 * 96  + 255) / 256, 256>>>(proj_w, 96, 96);
    transpose_w<2><<<(96 * 384 + 255) / 256, 256>>>(fc1_w,  96, 384);
    transpose_w<3><<<(384 * 96 + 255) / 256, 256>>>(fc2_w,  384, 96);

    ln_kernel<true><<<LTOK / 8, 256>>>(x, n1g, n1b);

    gemm_mma<0><<<dim3(3, 686), 256, GEMM_SMEM>>>(qkv_b, nullptr, nullptr, 96);

    attn_kernel<<<NWIN * NHEAD, 704, attn_smem>>>(rpb);

    gemm_mma<1><<<dim3(1, 686), 256, GEMM_SMEM>>>(proj_b, x, nullptr, 96);

    ln_kernel<false><<<LTOK / 8, 256>>>(x, n2g, n2b);

    gemm_mma<2><<<dim3(4, 686), 256, GEMM_SMEM>>>(fc1_b, nullptr, nullptr, 96);

    gemm_mma<3><<<dim3(1, 686), 256, GEMM_SMEM>>>(fc2_b, nullptr, out, 384);
}

// round 4
// speedup vs baseline: 2.3293x; 1.7080x over previous
#include <cuda_runtime.h>
#include <cstdint>

// ---------------------------------------------------------------------------
// Problem constants
// ---------------------------------------------------------------------------
#define HH   56
#define WWID 56
#define DDEP 28
#define LTOK 87808          // 56*56*28
#define CDIM 96
#define NWIN 256
#define NTOK 343
#define NHEAD 3
#define FF   384
#define BN   96             // GEMM N tile
#define BM   128            // GEMM M tile
#define KPAD 36             // smem row stride (floats)

// ---------------------------------------------------------------------------
// Scratch (device globals; no allocation allowed)
// ---------------------------------------------------------------------------
__device__ __align__(16) float g_H  [(size_t)LTOK * CDIM];
__device__ __align__(16) float g_QKV[(size_t)LTOK * 288];
__device__ __align__(16) float g_O  [(size_t)LTOK * CDIM];
__device__ __align__(16) float g_X  [(size_t)LTOK * CDIM];
__device__ __align__(16) float g_X2 [(size_t)LTOK * CDIM];
__device__ __align__(16) float g_FF [(size_t)LTOK * FF];
__device__ int g_DST[LTOK];
// pre-transposed weights [N,K]
__device__ __align__(16) float g_WtQKV [288 * 96];
__device__ __align__(16) float g_WtPROJ[96 * 96];
__device__ __align__(16) float g_WtFC1 [384 * 96];
__device__ __align__(16) float g_WtFC2 [96 * 384];

// ---------------------------------------------------------------------------
// helpers
// ---------------------------------------------------------------------------
__device__ __forceinline__ uint32_t f2tf32(float x) {
    uint32_t u;
    asm("cvt.rna.tf32.f32 %0, %1;" : "=r"(u) : "f"(x));
    return u;
}
__device__ __forceinline__ void mma8(float* c, const uint32_t* a, uint32_t b0, uint32_t b1) {
    asm("mma.sync.aligned.m16n8k8.row.col.f32.tf32.tf32.f32 "
        "{%0,%1,%2,%3}, {%4,%5,%6,%7}, {%8,%9}, {%0,%1,%2,%3};"
        : "+f"(c[0]), "+f"(c[1]), "+f"(c[2]), "+f"(c[3])
        : "r"(a[0]), "r"(a[1]), "r"(a[2]), "r"(a[3]), "r"(b0), "r"(b1));
}

// ---------------------------------------------------------------------------
// LayerNorm (one warp per token)
// ---------------------------------------------------------------------------
template <bool PERM>
__global__ void __launch_bounds__(256) ln_kernel(const float* __restrict__ in,
                                                 const float* __restrict__ gamma,
                                                 const float* __restrict__ beta)
{
    int gw   = (blockIdx.x * 256 + threadIdx.x) >> 5;
    int lane = threadIdx.x & 31;
    if (gw >= LTOK) return;

    const float* inp;
    float* outp;
    if (PERM) {
        int w = gw / NTOK, n = gw - w * NTOK;
        int iH = w >> 5, iW = (w >> 2) & 7, iD = w & 3;
        int a = n / 49; int r = n - a * 49; int b = r / 7; int c = r - b * 7;
        int th = iH * 7 + a + 3; if (th >= HH)   th -= HH;
        int tw = iW * 7 + b + 3; if (tw >= WWID) tw -= WWID;
        int td = iD * 7 + c + 3; if (td >= DDEP) td -= DDEP;
        int src = (th * WWID + tw) * DDEP + td;
        if (lane == 0) g_DST[gw] = src;
        inp  = in + (size_t)src * CDIM;
        outp = g_H + (size_t)gw * CDIM;
    } else {
        inp  = g_X + (size_t)gw * CDIM;
        outp = g_X2 + (size_t)gw * CDIM;
    }

    float v0 = inp[lane], v1 = inp[lane + 32], v2 = inp[lane + 64];
    float s  = v0 + v1 + v2;
    float ss = fmaf(v0, v0, fmaf(v1, v1, v2 * v2));
#pragma unroll
    for (int o = 16; o; o >>= 1) {
        s  += __shfl_xor_sync(0xffffffffu, s, o);
        ss += __shfl_xor_sync(0xffffffffu, ss, o);
    }
    float mean = s * (1.0f / 96.0f);
    float var  = ss * (1.0f / 96.0f) - mean * mean;
    float inv  = rsqrtf(var + 1e-5f);
    outp[lane]      = (v0 - mean) * inv * gamma[lane]      + beta[lane];
    outp[lane + 32] = (v1 - mean) * inv * gamma[lane + 32] + beta[lane + 32];
    outp[lane + 64] = (v2 - mean) * inv * gamma[lane + 64] + beta[lane + 64];
}

// ---------------------------------------------------------------------------
// Weight transpose W[K,N] -> Wt[N,K]
// ---------------------------------------------------------------------------
template <int MODE>
__global__ void transpose_w(const float* __restrict__ W, int K, int N)
{
    float* Wt = (MODE == 0) ? g_WtQKV : (MODE == 1) ? g_WtPROJ
              : (MODE == 2) ? g_WtFC1 : g_WtFC2;
    int idx = blockIdx.x * 256 + threadIdx.x;
    if (idx < K * N) {
        int k = idx / N, n = idx - k * N;
        Wt[n * K + k] = W[idx];
    }
}

// ---------------------------------------------------------------------------
// mma.sync tf32 GEMM: C[128,96] = A[128,K] @ Wt[96,K]^T (+ epilogue)
// ---------------------------------------------------------------------------
#define GEMM_SMEM 49664

template <int MODE>
__global__ void __launch_bounds__(256) gemm_mma(const float* __restrict__ bias,
                                                const float* __restrict__ res,
                                                float* __restrict__ outp,
                                                int K)
{
    extern __shared__ __align__(16) char smraw[];
    uint32_t* Asu = (uint32_t*)smraw;                 // [128][36]
    uint32_t* Bsu = (uint32_t*)(smraw + 18432);       // [96][36]
    float*    Sf  = (float*)smraw;                    // epilogue [128][97]

    const float* A  = (MODE == 0) ? g_H : (MODE == 1) ? g_O : (MODE == 2) ? g_X2 : g_FF;
    const float* Wt = (MODE == 0) ? g_WtQKV : (MODE == 1) ? g_WtPROJ
                    : (MODE == 2) ? g_WtFC1 : g_WtFC2;

    int tid  = threadIdx.x;
    int wid  = tid >> 5, lane = tid & 31;
    int wr   = wid >> 1, wc = wid & 1;
    int g    = lane >> 2, c = lane & 3;
    int m0   = blockIdx.y * BM;
    int n0   = blockIdx.x * BN;

    float acc[2][6][4];
#pragma unroll
    for (int t = 0; t < 2; t++)
#pragma unroll
        for (int u = 0; u < 6; u++)
#pragma unroll
            for (int j = 0; j < 4; j++) acc[t][u][j] = 0.0f;

    int nc = K >> 5;
    for (int ch = 0; ch < nc; ch++) {
        int k0 = ch << 5;
        __syncthreads();
#pragma unroll
        for (int i = 0; i < 4; i++) {
            int idx = tid + (i << 8);
            int row = idx >> 3, q = idx & 7;
            float4 v = *(const float4*)(A + (size_t)(m0 + row) * K + k0 + (q << 2));
            uint4 u4; u4.x = f2tf32(v.x); u4.y = f2tf32(v.y); u4.z = f2tf32(v.z); u4.w = f2tf32(v.w);
            *(uint4*)(Asu + row * KPAD + (q << 2)) = u4;
        }
#pragma unroll
        for (int i = 0; i < 3; i++) {
            int idx = tid + (i << 8);
            int row = idx >> 3, q = idx & 7;
            float4 v = *(const float4*)(Wt + (size_t)(n0 + row) * K + k0 + (q << 2));
            uint4 u4; u4.x = f2tf32(v.x); u4.y = f2tf32(v.y); u4.z = f2tf32(v.z); u4.w = f2tf32(v.w);
            *(uint4*)(Bsu + row * KPAD + (q << 2)) = u4;
        }
        __syncthreads();

#pragma unroll
        for (int ks = 0; ks < 4; ks++) {
            int kk = (ks << 3) + c;
            uint32_t a[2][4];
#pragma unroll
            for (int t = 0; t < 2; t++) {
                int r0 = wr * 32 + t * 16 + g;
                a[t][0] = Asu[r0 * KPAD + kk];
                a[t][1] = Asu[(r0 + 8) * KPAD + kk];
                a[t][2] = Asu[r0 * KPAD + kk + 4];
                a[t][3] = Asu[(r0 + 8) * KPAD + kk + 4];
            }
#pragma unroll
            for (int u = 0; u < 6; u++) {
                int nb = wc * 48 + u * 8 + g;
                uint32_t b0 = Bsu[nb * KPAD + kk];
                uint32_t b1 = Bsu[nb * KPAD + kk + 4];
                mma8(acc[0][u], a[0], b0, b1);
                mma8(acc[1][u], a[1], b0, b1);
            }
        }
    }
    __syncthreads();

#pragma unroll
    for (int t = 0; t < 2; t++) {
#pragma unroll
        for (int u = 0; u < 6; u++) {
            int r0 = wr * 32 + t * 16 + g;
            int nn = wc * 48 + u * 8 + 2 * c;
            float b0 = __ldg(bias + n0 + nn);
            float b1 = __ldg(bias + n0 + nn + 1);
            float v0 = acc[t][u][0] + b0, v1 = acc[t][u][1] + b1;
            float v2 = acc[t][u][2] + b0, v3 = acc[t][u][3] + b1;
            if (MODE == 0 && n0 == 0) {
                v0 *= 0.17677669529663689f; v1 *= 0.17677669529663689f;
                v2 *= 0.17677669529663689f; v3 *= 0.17677669529663689f;
            }
            if (MODE == 2) {
                v0 = 0.5f * v0 * (1.0f + erff(v0 * 0.70710678118654752f));
                v1 = 0.5f * v1 * (1.0f + erff(v1 * 0.70710678118654752f));
                v2 = 0.5f * v2 * (1.0f + erff(v2 * 0.70710678118654752f));
                v3 = 0.5f * v3 * (1.0f + erff(v3 * 0.70710678118654752f));
            }
            Sf[r0 * 97 + nn] = v0;       Sf[r0 * 97 + nn + 1] = v1;
            Sf[(r0 + 8) * 97 + nn] = v2; Sf[(r0 + 8) * 97 + nn + 1] = v3;
        }
    }
    __syncthreads();

#pragma unroll
    for (int i = 0; i < 12; i++) {
        int idx = tid + (i << 8);
        int row = idx / 24, q4 = idx - row * 24;
        int m = m0 + row, n = n0 + (q4 << 2);
        const float* sp = Sf + row * 97 + (q4 << 2);
        float4 v; v.x = sp[0]; v.y = sp[1]; v.z = sp[2]; v.w = sp[3];
        if (MODE == 0) {
            *(float4*)(g_QKV + (size_t)m * 288 + n) = v;
        } else if (MODE == 1) {
            int d0 = g_DST[m];
            float4 r = *(const float4*)(res + (size_t)d0 * 96 + n);
            v.x += r.x; v.y += r.y; v.z += r.z; v.w += r.w;
            *(float4*)(g_X + (size_t)d0 * 96 + n) = v;
        } else if (MODE == 2) {
            *(float4*)(g_FF + (size_t)m * 384 + n) = v;
        } else {
            float4 r = *(const float4*)(g_X + (size_t)m * 96 + n);
            v.x += r.x; v.y += r.y; v.z += r.z; v.w += r.w;
            *(float4*)(outp + (size_t)m * 96 + n) = v;
        }
    }
}

// ---------------------------------------------------------------------------
// MMA attention: block = (window, head), 352 threads = 11 warps,
// warp owns 32 query rows. Flash-style over key chunks of 32.
// smem: Qs/Ks/Vs [352][36] tf32, bias table, meta.
// ---------------------------------------------------------------------------
#define NPAD 352
#define ASTRIDE 36
#define ATTN_SMEM (3 * NPAD * ASTRIDE * 4 + 2197 * 4 + NPAD * 4)

__global__ void __launch_bounds__(352, 1) attn_mma(const float* __restrict__ rpb)
{
    extern __shared__ __align__(16) char smraw[];
    uint32_t* Qs = (uint32_t*)smraw;                          // [352][36]
    uint32_t* Ks = Qs + NPAD * ASTRIDE;
    uint32_t* Vs = Ks + NPAD * ASTRIDE;
    float*    Bf = (float*)(Vs + NPAD * ASTRIDE);             // [2197]
    int*      Ms = (int*)(Bf + 2197);                         // [352]

    int w   = blockIdx.x / 3;
    int h   = blockIdx.x - w * 3;
    int tid = threadIdx.x;
    const float* base = g_QKV + (size_t)w * NTOK * 288;

    for (int i = tid; i < NTOK * 32; i += 352) {
        int n = i >> 5, j = i & 31;
        const float* bp = base + n * 288 + h * 32 + j;
        Qs[n * ASTRIDE + j] = f2tf32(bp[0]);
        Ks[n * ASTRIDE + j] = f2tf32(bp[96]);
        Vs[n * ASTRIDE + j] = f2tf32(bp[192]);
    }
    for (int i = NTOK * 32 + tid; i < NPAD * 32; i += 352) {
        int n = i >> 5, j = i & 31;
        Qs[n * ASTRIDE + j] = 0;
        Ks[n * ASTRIDE + j] = 0;
        Vs[n * ASTRIDE + j] = 0;
    }
    for (int i = tid; i < 2197; i += 352)
        Bf[i] = rpb[i * 3 + h];

    int iH = w >> 5, iW = (w >> 2) & 7, iD = w & 3;
    for (int m = tid; m < NPAD; m += 352) {
        if (m < NTOK) {
            int a = m / 49; int r = m - a * 49; int b = r / 7; int c = r - b * 7;
            int sub = a * 169 + b * 13 + c;
            int ph = iH * 7 + a, pw = iW * 7 + b, pd = iD * 7 + c;
            int rh = (ph < 49) ? 0 : ((ph < 53) ? 1 : 2);
            int rw = (pw < 49) ? 0 : ((pw < 53) ? 1 : 2);
            int rd = (pd < 21) ? 0 : ((pd < 25) ? 1 : 2);
            Ms[m] = sub | (((rh * 3 + rw) * 3 + rd) << 16);
        } else {
            Ms[m] = 0;
        }
    }
    __syncthreads();

    int wid  = tid >> 5, lane = tid & 31;
    int g    = lane >> 2, c = lane & 3;
    int q0   = wid * 32;

    // preload Q fragments (invariant over key chunks)
    uint32_t qa[2][4][4];
#pragma unroll
    for (int t = 0; t < 2; t++) {
        int r0 = q0 + t * 16 + g;
#pragma unroll
        for (int kk = 0; kk < 4; kk++) {
            int kc8 = kk * 8 + c;
            qa[t][kk][0] = Qs[r0 * ASTRIDE + kc8];
            qa[t][kk][1] = Qs[(r0 + 8) * ASTRIDE + kc8];
            qa[t][kk][2] = Qs[r0 * ASTRIDE + kc8 + 4];
            qa[t][kk][3] = Qs[(r0 + 8) * ASTRIDE + kc8 + 4];
        }
    }

    // per-row meta (4 owned rows: t*2 + rr, row = q0 + t*16 + g + 8*rr)
    int ibq[4], cnq[4];
#pragma unroll
    for (int ri = 0; ri < 4; ri++) {
        int row = q0 + (ri >> 1) * 16 + g + (ri & 1) * 8;
        int mv = Ms[row];
        ibq[ri] = (mv & 0xffff) + 1098;
        cnq[ri] = mv >> 16;
    }

    float mrun[4] = {-1e30f, -1e30f, -1e30f, -1e30f};
    float lrun[4] = {0.f, 0.f, 0.f, 0.f};
    float o[2][4][4];
#pragma unroll
    for (int t = 0; t < 2; t++)
#pragma unroll
        for (int nb = 0; nb < 4; nb++)
#pragma unroll
            for (int j = 0; j < 4; j++) o[t][nb][j] = 0.f;

    for (int kc = 0; kc < NPAD; kc += 32) {
        // key meta for owned columns
        int km[8];
#pragma unroll
        for (int nb = 0; nb < 4; nb++) {
#pragma unroll
            for (int e = 0; e < 2; e++)
                km[nb * 2 + e] = Ms[kc + nb * 8 + 2 * c + e];
        }

        // S = Q K^T (32 queries x 32 keys per warp)
        float sa[2][4][4];
#pragma unroll
        for (int t = 0; t < 2; t++)
#pragma unroll
            for (int nb = 0; nb < 4; nb++)
#pragma unroll
                for (int j = 0; j < 4; j++) sa[t][nb][j] = 0.f;

#pragma unroll
        for (int nb = 0; nb < 4; nb++) {
            int krow = kc + nb * 8 + g;
#pragma unroll
            for (int kk = 0; kk < 4; kk++) {
                uint32_t b0 = Ks[krow * ASTRIDE + kk * 8 + c];
                uint32_t b1 = Ks[krow * ASTRIDE + kk * 8 + c + 4];
                mma8(sa[0][nb], qa[0][kk], b0, b1);
                mma8(sa[1][nb], qa[1][kk], b0, b1);
            }
        }

        // bias + mask + padding
#pragma unroll
        for (int t = 0; t < 2; t++) {
#pragma unroll
            for (int nb = 0; nb < 4; nb++) {
#pragma unroll
                for (int sl = 0; sl < 4; sl++) {
                    int e  = sl & 1;
                    int ri = t * 2 + (sl >> 1);
                    int j  = kc + nb * 8 + 2 * c + e;
                    int kv = km[nb * 2 + e];
                    float s = sa[t][nb][sl] + Bf[ibq[ri] - (kv & 0xffff)];
                    if (cnq[ri] != (kv >> 16)) s -= 100.0f;
                    if (j >= NTOK) s = -30000.0f;
                    sa[t][nb][sl] = s;
                }
            }
        }

        // online softmax per row
#pragma unroll
        for (int ri = 0; ri < 4; ri++) {
            int t = ri >> 1, rr = ri & 1;
            float mx = -3e4f;
#pragma unroll
            for (int nb = 0; nb < 4; nb++)
                mx = fmaxf(mx, fmaxf(sa[t][nb][rr * 2], sa[t][nb][rr * 2 + 1]));
            mx = fmaxf(mx, __shfl_xor_sync(0xffffffffu, mx, 1));
            mx = fmaxf(mx, __shfl_xor_sync(0xffffffffu, mx, 2));
            float mnew = fmaxf(mrun[ri], mx);
            float corr = __expf(mrun[ri] - mnew);
            mrun[ri] = mnew;
            float ls = 0.f;
#pragma unroll
            for (int nb = 0; nb < 4; nb++) {
                float p0 = __expf(sa[t][nb][rr * 2]     - mnew);
                float p1 = __expf(sa[t][nb][rr * 2 + 1] - mnew);
                sa[t][nb][rr * 2]     = p0;
                sa[t][nb][rr * 2 + 1] = p1;
                ls += p0 + p1;
            }
            ls += __shfl_xor_sync(0xffffffffu, ls, 1);
            ls += __shfl_xor_sync(0xffffffffu, ls, 2);
            lrun[ri] = lrun[ri] * corr + ls;
#pragma unroll
            for (int nb = 0; nb < 4; nb++) {
                o[t][nb][rr * 2]     *= corr;
                o[t][nb][rr * 2 + 1] *= corr;
            }
        }

        // P -> A fragments (shfl re-layout), PV mma
        int src0 = (lane & ~3) | (c >> 1);
        int src1 = src0 + 2;
        int par  = c & 1;
#pragma unroll
        for (int kb = 0; kb < 4; kb++) {
            uint32_t ua[2][4];
#pragma unroll
            for (int t = 0; t < 2; t++) {
                float v00 = __shfl_sync(0xffffffffu, sa[t][kb][0], src0);
                float v01 = __shfl_sync(0xffffffffu, sa[t][kb][1], src0);
                float v10 = __shfl_sync(0xffffffffu, sa[t][kb][2], src0);
                float v11 = __shfl_sync(0xffffffffu, sa[t][kb][3], src0);
                float w00 = __shfl_sync(0xffffffffu, sa[t][kb][0], src1);
                float w01 = __shfl_sync(0xffffffffu, sa[t][kb][1], src1);
                float w10 = __shfl_sync(0xffffffffu, sa[t][kb][2], src1);
                float w11 = __shfl_sync(0xffffffffu, sa[t][kb][3], src1);
                ua[t][0] = f2tf32(par ? v01 : v00);
                ua[t][1] = f2tf32(par ? v11 : v10);
                ua[t][2] = f2tf32(par ? w01 : w00);
                ua[t][3] = f2tf32(par ? w11 : w10);
            }
            int vr0 = kc + kb * 8 + c;
#pragma unroll
            for (int nb = 0; nb < 4; nb++) {
                uint32_t b0 = Vs[vr0 * ASTRIDE + nb * 8 + g];
                uint32_t b1 = Vs[(vr0 + 4) * ASTRIDE + nb * 8 + g];
                mma8(o[0][nb], ua[0], b0, b1);
                mma8(o[1][nb], ua[1], b0, b1);
            }
        }
    }

    // store
    float inv[4];
#pragma unroll
    for (int ri = 0; ri < 4; ri++) inv[ri] = 1.0f / lrun[ri];

#pragma unroll
    for (int t = 0; t < 2; t++) {
        int r0 = q0 + t * 16 + g;
#pragma unroll
        for (int rr = 0; rr < 2; rr++) {
            int row = r0 + rr * 8;
            if (row < NTOK) {
                int ri = t * 2 + rr;
                float* op = g_O + ((size_t)w * NTOK + row) * CDIM + h * 32;
#pragma unroll
                for (int nb = 0; nb < 4; nb++) {
                    float2 st;
                    st.x = o[t][nb][rr * 2]     * inv[ri];
                    st.y = o[t][nb][rr * 2 + 1] * inv[ri];
                    *(float2*)(op + nb * 8 + 2 * c) = st;
                }
            }
        }
    }
}

// ---------------------------------------------------------------------------
// Launch
// ---------------------------------------------------------------------------
extern "C" void kernel_launch(void* const* d_in, const int* in_sizes, int n_in,
                              void* d_out, int out_size)
{
    const float* x      = (const float*)d_in[0];
    const float* n1g    = (const float*)d_in[1];
    const float* n1b    = (const float*)d_in[2];
    const float* qkv_w  = (const float*)d_in[3];
    const float* qkv_b  = (const float*)d_in[4];
    const float* rpb    = (const float*)d_in[5];
    const float* proj_w = (const float*)d_in[6];
    const float* proj_b = (const float*)d_in[7];
    const float* n2g    = (const float*)d_in[8];
    const float* n2b    = (const float*)d_in[9];
    const float* fc1_w  = (const float*)d_in[10];
    const float* fc1_b  = (const float*)d_in[11];
    const float* fc2_w  = (const float*)d_in[12];
    const float* fc2_b  = (const float*)d_in[13];
    float* out = (float*)d_out;

    cudaFuncSetAttribute(gemm_mma<0>, cudaFuncAttributeMaxDynamicSharedMemorySize, GEMM_SMEM);
    cudaFuncSetAttribute(gemm_mma<1>, cudaFuncAttributeMaxDynamicSharedMemorySize, GEMM_SMEM);
    cudaFuncSetAttribute(gemm_mma<2>, cudaFuncAttributeMaxDynamicSharedMemorySize, GEMM_SMEM);
    cudaFuncSetAttribute(gemm_mma<3>, cudaFuncAttributeMaxDynamicSharedMemorySize, GEMM_SMEM);
    cudaFuncSetAttribute(attn_mma, cudaFuncAttributeMaxDynamicSharedMemorySize, ATTN_SMEM);

    transpose_w<0><<<(96 * 288 + 255) / 256, 256>>>(qkv_w,  96, 288);
    transpose_w<1><<<(96 * 96  + 255) / 256, 256>>>(proj_w, 96, 96);
    transpose_w<2><<<(96 * 384 + 255) / 256, 256>>>(fc1_w,  96, 384);
    transpose_w<3><<<(384 * 96 + 255) / 256, 256>>>(fc2_w,  384, 96);

    ln_kernel<true><<<LTOK / 8, 256>>>(x, n1g, n1b);

    gemm_mma<0><<<dim3(3, 686), 256, GEMM_SMEM>>>(qkv_b, nullptr, nullptr, 96);

    attn_mma<<<NWIN * NHEAD, 352, ATTN_SMEM>>>(rpb);

    gemm_mma<1><<<dim3(1, 686), 256, GEMM_SMEM>>>(proj_b, x, nullptr, 96);

    ln_kernel<false><<<LTOK / 8, 256>>>(x, n2g, n2b);

    gemm_mma<2><<<dim3(4, 686), 256, GEMM_SMEM>>>(fc1_b, nullptr, nullptr, 96);

    gemm_mma<3><<<dim3(1, 686), 256, GEMM_SMEM>>>(fc2_b, nullptr, out, 384);
}

// round 5
// speedup vs baseline: 2.4710x; 1.0608x over previous
#include <cuda_runtime.h>
#include <cstdint>

// ---------------------------------------------------------------------------
// Problem constants
// ---------------------------------------------------------------------------
#define HH   56
#define WWID 56
#define DDEP 28
#define LTOK 87808          // 56*56*28
#define CDIM 96
#define NWIN 256
#define NTOK 343
#define NHEAD 3
#define FF   384
#define BN   96             // GEMM N tile
#define BM   128            // GEMM M tile
#define KPAD 36             // smem row stride (floats)

// ---------------------------------------------------------------------------
// Scratch (device globals; no allocation allowed)
// ---------------------------------------------------------------------------
__device__ __align__(16) float g_H  [(size_t)LTOK * CDIM];
__device__ __align__(16) float g_QKV[(size_t)LTOK * 288];
__device__ __align__(16) float g_O  [(size_t)LTOK * CDIM];
__device__ __align__(16) float g_X  [(size_t)LTOK * CDIM];
__device__ __align__(16) float g_X2 [(size_t)LTOK * CDIM];
__device__ __align__(16) float g_FF [(size_t)LTOK * FF];
__device__ int g_DST[LTOK];
// pre-transposed weights [N,K]
__device__ __align__(16) float g_WtQKV [288 * 96];
__device__ __align__(16) float g_WtPROJ[96 * 96];
__device__ __align__(16) float g_WtFC1 [384 * 96];
__device__ __align__(16) float g_WtFC2 [96 * 384];

// ---------------------------------------------------------------------------
// helpers
// ---------------------------------------------------------------------------
__device__ __forceinline__ uint32_t f2tf32(float x) {
    uint32_t u;
    asm("cvt.rna.tf32.f32 %0, %1;" : "=r"(u) : "f"(x));
    return u;
}
__device__ __forceinline__ void mma8(float* c, const uint32_t* a, uint32_t b0, uint32_t b1) {
    asm("mma.sync.aligned.m16n8k8.row.col.f32.tf32.tf32.f32 "
        "{%0,%1,%2,%3}, {%4,%5,%6,%7}, {%8,%9}, {%0,%1,%2,%3};"
        : "+f"(c[0]), "+f"(c[1]), "+f"(c[2]), "+f"(c[3])
        : "r"(a[0]), "r"(a[1]), "r"(a[2]), "r"(a[3]), "r"(b0), "r"(b1));
}

// ---------------------------------------------------------------------------
// LayerNorm #1 (one warp per token): gather + shift + window partition
// ---------------------------------------------------------------------------
__global__ void __launch_bounds__(256) ln_kernel(const float* __restrict__ in,
                                                 const float* __restrict__ gamma,
                                                 const float* __restrict__ beta)
{
    int gw   = (blockIdx.x * 256 + threadIdx.x) >> 5;
    int lane = threadIdx.x & 31;
    if (gw >= LTOK) return;

    int w = gw / NTOK, n = gw - w * NTOK;
    int iH = w >> 5, iW = (w >> 2) & 7, iD = w & 3;
    int a = n / 49; int r = n - a * 49; int b = r / 7; int c = r - b * 7;
    int th = iH * 7 + a + 3; if (th >= HH)   th -= HH;
    int tw = iW * 7 + b + 3; if (tw >= WWID) tw -= WWID;
    int td = iD * 7 + c + 3; if (td >= DDEP) td -= DDEP;
    int src = (th * WWID + tw) * DDEP + td;
    if (lane == 0) g_DST[gw] = src;
    const float* inp  = in + (size_t)src * CDIM;
    float* outp = g_H + (size_t)gw * CDIM;

    float v0 = inp[lane], v1 = inp[lane + 32], v2 = inp[lane + 64];
    float s  = v0 + v1 + v2;
    float ss = fmaf(v0, v0, fmaf(v1, v1, v2 * v2));
#pragma unroll
    for (int o = 16; o; o >>= 1) {
        s  += __shfl_xor_sync(0xffffffffu, s, o);
        ss += __shfl_xor_sync(0xffffffffu, ss, o);
    }
    float mean = s * (1.0f / 96.0f);
    float var  = ss * (1.0f / 96.0f) - mean * mean;
    float inv  = rsqrtf(var + 1e-5f);
    outp[lane]      = (v0 - mean) * inv * gamma[lane]      + beta[lane];
    outp[lane + 32] = (v1 - mean) * inv * gamma[lane + 32] + beta[lane + 32];
    outp[lane + 64] = (v2 - mean) * inv * gamma[lane + 64] + beta[lane + 64];
}

// ---------------------------------------------------------------------------
// All weight transposes in one launch: W[K,N] -> Wt[N,K]
// ---------------------------------------------------------------------------
__global__ void transpose_all(const float* __restrict__ qkv_w,
                              const float* __restrict__ proj_w,
                              const float* __restrict__ fc1_w,
                              const float* __restrict__ fc2_w)
{
    int idx = blockIdx.x * 256 + threadIdx.x;
    if (idx < 27648) {                       // qkv 96x288
        int k = idx / 288, n = idx - k * 288;
        g_WtQKV[n * 96 + k] = qkv_w[idx];
    } else if (idx < 36864) {                // proj 96x96
        int j = idx - 27648;
        int k = j / 96, n = j - k * 96;
        g_WtPROJ[n * 96 + k] = proj_w[j];
    } else if (idx < 73728) {                // fc1 96x384
        int j = idx - 36864;
        int k = j / 384, n = j - k * 384;
        g_WtFC1[n * 96 + k] = fc1_w[j];
    } else if (idx < 110592) {               // fc2 384x96
        int j = idx - 73728;
        int k = j / 96, n = j - k * 96;
        g_WtFC2[n * 384 + k] = fc2_w[j];
    }
}

// ---------------------------------------------------------------------------
// Double-buffered mma.sync tf32 GEMM: C[128,96] = A[128,K] @ Wt[96,K]^T
// Register prefetch of chunk c+1 overlaps mma of chunk c.
// MODE 0: qkv (q-scale)  MODE 1: proj (scatter+residual + fused LN2)
// MODE 2: fc1 (GELU)     MODE 3: fc2 (+residual -> d_out)
// ---------------------------------------------------------------------------
#define ABUF 4608            // 128*36 words
#define BBUF 3456            // 96*36 words
#define GEMM_SMEM ((2 * ABUF + 2 * BBUF) * 4)   // 64512 B; epilogue aliases

template <int MODE>
__global__ void __launch_bounds__(256) gemm_mma(const float* __restrict__ bias,
                                                const float* __restrict__ res,
                                                float* __restrict__ outp,
                                                int K,
                                                const float* __restrict__ g2,
                                                const float* __restrict__ b2)
{
    extern __shared__ __align__(16) char smraw[];
    uint32_t* Au = (uint32_t*)smraw;                  // [2][128][36]
    uint32_t* Bu = (uint32_t*)(smraw + 2 * ABUF * 4); // [2][96][36]
    float*    Sf = (float*)smraw;                     // epilogue [128][97]

    const float* A  = (MODE == 0) ? g_H : (MODE == 1) ? g_O : (MODE == 2) ? g_X2 : g_FF;
    const float* Wt = (MODE == 0) ? g_WtQKV : (MODE == 1) ? g_WtPROJ
                    : (MODE == 2) ? g_WtFC1 : g_WtFC2;

    int tid  = threadIdx.x;
    int wid  = tid >> 5, lane = tid & 31;
    int wr   = wid >> 1, wc = wid & 1;
    int g    = lane >> 2, c = lane & 3;
    int m0   = blockIdx.y * BM;
    int n0   = blockIdx.x * BN;

    // per-thread staging coordinates
    int arow = tid >> 3, aq = (tid & 7) << 2;            // + i*32 rows
    const float* Aptr = A + (size_t)(m0 + arow) * K + aq;
    int brow = tid >> 3;                                  // + i*32 rows
    const float* Bptr = Wt + (size_t)(n0 + brow) * K + aq;

    float4 ra[4], rb[3];
#pragma unroll
    for (int i = 0; i < 4; i++)
        ra[i] = *(const float4*)(Aptr + (size_t)(i << 5) * K);
#pragma unroll
    for (int i = 0; i < 3; i++)
        rb[i] = *(const float4*)(Bptr + (size_t)(i << 5) * K);

    // store chunk into buffer b
    auto stage = [&](int b) {
        uint32_t* Ad = Au + b * ABUF;
        uint32_t* Bd = Bu + b * BBUF;
#pragma unroll
        for (int i = 0; i < 4; i++) {
            uint4 u; u.x = f2tf32(ra[i].x); u.y = f2tf32(ra[i].y);
            u.z = f2tf32(ra[i].z); u.w = f2tf32(ra[i].w);
            *(uint4*)(Ad + (arow + (i << 5)) * KPAD + aq) = u;
        }
#pragma unroll
        for (int i = 0; i < 3; i++) {
            uint4 u; u.x = f2tf32(rb[i].x); u.y = f2tf32(rb[i].y);
            u.z = f2tf32(rb[i].z); u.w = f2tf32(rb[i].w);
            *(uint4*)(Bd + (brow + (i << 5)) * KPAD + aq) = u;
        }
    };

    stage(0);
    __syncthreads();

    float acc[2][6][4];
#pragma unroll
    for (int t = 0; t < 2; t++)
#pragma unroll
        for (int u = 0; u < 6; u++)
#pragma unroll
            for (int j = 0; j < 4; j++) acc[t][u][j] = 0.0f;

    int nc = K >> 5;
    for (int ch = 0; ch < nc; ch++) {
        if (ch + 1 < nc) {
            int k1 = (ch + 1) << 5;
#pragma unroll
            for (int i = 0; i < 4; i++)
                ra[i] = *(const float4*)(Aptr + (size_t)(i << 5) * K + k1);
#pragma unroll
            for (int i = 0; i < 3; i++)
                rb[i] = *(const float4*)(Bptr + (size_t)(i << 5) * K + k1);
        }
        const uint32_t* As = Au + (ch & 1) * ABUF;
        const uint32_t* Bs = Bu + (ch & 1) * BBUF;
#pragma unroll
        for (int ks = 0; ks < 4; ks++) {
            int kk = (ks << 3) + c;
            uint32_t a[2][4];
#pragma unroll
            for (int t = 0; t < 2; t++) {
                int r0 = wr * 32 + t * 16 + g;
                a[t][0] = As[r0 * KPAD + kk];
                a[t][1] = As[(r0 + 8) * KPAD + kk];
                a[t][2] = As[r0 * KPAD + kk + 4];
                a[t][3] = As[(r0 + 8) * KPAD + kk + 4];
            }
#pragma unroll
            for (int u = 0; u < 6; u++) {
                int nb = wc * 48 + u * 8 + g;
                uint32_t b0 = Bs[nb * KPAD + kk];
                uint32_t b1 = Bs[nb * KPAD + kk + 4];
                mma8(acc[0][u], a[0], b0, b1);
                mma8(acc[1][u], a[1], b0, b1);
            }
        }
        if (ch + 1 < nc) {
            stage((ch + 1) & 1);
            __syncthreads();
        }
    }
    __syncthreads();   // protect epilogue aliasing of the buffers

    // Epilogue: registers -> staged smem [128][97] with bias/scale/GELU
#pragma unroll
    for (int t = 0; t < 2; t++) {
#pragma unroll
        for (int u = 0; u < 6; u++) {
            int r0 = wr * 32 + t * 16 + g;
            int nn = wc * 48 + u * 8 + 2 * c;
            float b0 = __ldg(bias + n0 + nn);
            float b1 = __ldg(bias + n0 + nn + 1);
            float v0 = acc[t][u][0] + b0, v1 = acc[t][u][1] + b1;
            float v2 = acc[t][u][2] + b0, v3 = acc[t][u][3] + b1;
            if (MODE == 0 && n0 == 0) {
                v0 *= 0.17677669529663689f; v1 *= 0.17677669529663689f;
                v2 *= 0.17677669529663689f; v3 *= 0.17677669529663689f;
            }
            if (MODE == 2) {
                v0 = 0.5f * v0 * (1.0f + erff(v0 * 0.70710678118654752f));
                v1 = 0.5f * v1 * (1.0f + erff(v1 * 0.70710678118654752f));
                v2 = 0.5f * v2 * (1.0f + erff(v2 * 0.70710678118654752f));
                v3 = 0.5f * v3 * (1.0f + erff(v3 * 0.70710678118654752f));
            }
            Sf[r0 * 97 + nn] = v0;       Sf[r0 * 97 + nn + 1] = v1;
            Sf[(r0 + 8) * 97 + nn] = v2; Sf[(r0 + 8) * 97 + nn + 1] = v3;
        }
    }
    __syncthreads();

    // Coalesced float4 stores (+ residual / scatter)
#pragma unroll
    for (int i = 0; i < 12; i++) {
        int idx = tid + (i << 8);
        int row = idx / 24, q4 = idx - row * 24;
        int m = m0 + row, n = n0 + (q4 << 2);
        float* sp = Sf + row * 97 + (q4 << 2);
        float4 v; v.x = sp[0]; v.y = sp[1]; v.z = sp[2]; v.w = sp[3];
        if (MODE == 0) {
            *(float4*)(g_QKV + (size_t)m * 288 + n) = v;
        } else if (MODE == 1) {
            int d0 = g_DST[m];
            float4 r = *(const float4*)(res + (size_t)d0 * 96 + n);
            v.x += r.x; v.y += r.y; v.z += r.z; v.w += r.w;
            *(float4*)(g_X + (size_t)d0 * 96 + n) = v;
            sp[0] = v.x; sp[1] = v.y; sp[2] = v.z; sp[3] = v.w;  // keep for LN2
        } else if (MODE == 2) {
            *(float4*)(g_FF + (size_t)m * 384 + n) = v;
        } else {
            float4 r = *(const float4*)(g_X + (size_t)m * 96 + n);
            v.x += r.x; v.y += r.y; v.z += r.z; v.w += r.w;
            *(float4*)(outp + (size_t)m * 96 + n) = v;
        }
    }

    // Fused LN2 (proj only): rows complete in Sf (grid.x == 1)
    if (MODE == 1) {
        __syncthreads();
        int row = tid >> 1, half = tid & 1;
        const float* rp = Sf + row * 97 + half * 48;
        float s = 0.f, ss = 0.f;
#pragma unroll
        for (int j = 0; j < 48; j++) {
            float v = rp[j];
            s += v; ss = fmaf(v, v, ss);
        }
        s  += __shfl_xor_sync(0xffffffffu, s, 1);
        ss += __shfl_xor_sync(0xffffffffu, ss, 1);
        float mean = s * (1.0f / 96.0f);
        float var  = ss * (1.0f / 96.0f) - mean * mean;
        float inv  = rsqrtf(var + 1e-5f);
        int d0 = g_DST[m0 + row];
        float* op = g_X2 + (size_t)d0 * 96 + half * 48;
#pragma unroll
        for (int j4 = 0; j4 < 12; j4++) {
            int n = half * 48 + j4 * 4;
            float4 o;
            o.x = (rp[j4 * 4]     - mean) * inv * __ldg(g2 + n)     + __ldg(b2 + n);
            o.y = (rp[j4 * 4 + 1] - mean) * inv * __ldg(g2 + n + 1) + __ldg(b2 + n + 1);
            o.z = (rp[j4 * 4 + 2] - mean) * inv * __ldg(g2 + n + 2) + __ldg(b2 + n + 2);
            o.w = (rp[j4 * 4 + 3] - mean) * inv * __ldg(g2 + n + 3) + __ldg(b2 + n + 3);
            *(float4*)(op + j4 * 4) = o;
        }
    }
}

// ---------------------------------------------------------------------------
// MMA attention: block = (window, head), 352 threads = 11 warps,
// warp owns 32 query rows. Flash-style over key chunks of 32.
// ---------------------------------------------------------------------------
#define NPAD 352
#define ASTRIDE 36
#define ATTN_SMEM (3 * NPAD * ASTRIDE * 4 + 2197 * 4 + NPAD * 4)

__global__ void __launch_bounds__(352, 1) attn_mma(const float* __restrict__ rpb)
{
    extern __shared__ __align__(16) char smraw[];
    uint32_t* Qs = (uint32_t*)smraw;                          // [352][36]
    uint32_t* Ks = Qs + NPAD * ASTRIDE;
    uint32_t* Vs = Ks + NPAD * ASTRIDE;
    float*    Bf = (float*)(Vs + NPAD * ASTRIDE);             // [2197]
    int*      Ms = (int*)(Bf + 2197);                         // [352]

    int w   = blockIdx.x / 3;
    int h   = blockIdx.x - w * 3;
    int tid = threadIdx.x;
    const float* base = g_QKV + (size_t)w * NTOK * 288;

    for (int i = tid; i < NTOK * 32; i += 352) {
        int n = i >> 5, j = i & 31;
        const float* bp = base + n * 288 + h * 32 + j;
        Qs[n * ASTRIDE + j] = f2tf32(bp[0]);
        Ks[n * ASTRIDE + j] = f2tf32(bp[96]);
        Vs[n * ASTRIDE + j] = f2tf32(bp[192]);
    }
    for (int i = NTOK * 32 + tid; i < NPAD * 32; i += 352) {
        int n = i >> 5, j = i & 31;
        Qs[n * ASTRIDE + j] = 0;
        Ks[n * ASTRIDE + j] = 0;
        Vs[n * ASTRIDE + j] = 0;
    }
    for (int i = tid; i < 2197; i += 352)
        Bf[i] = rpb[i * 3 + h];

    int iH = w >> 5, iW = (w >> 2) & 7, iD = w & 3;
    for (int m = tid; m < NPAD; m += 352) {
        if (m < NTOK) {
            int a = m / 49; int r = m - a * 49; int b = r / 7; int c = r - b * 7;
            int sub = a * 169 + b * 13 + c;
            int ph = iH * 7 + a, pw = iW * 7 + b, pd = iD * 7 + c;
            int rh = (ph < 49) ? 0 : ((ph < 53) ? 1 : 2);
            int rw = (pw < 49) ? 0 : ((pw < 53) ? 1 : 2);
            int rd = (pd < 21) ? 0 : ((pd < 25) ? 1 : 2);
            Ms[m] = sub | (((rh * 3 + rw) * 3 + rd) << 16);
        } else {
            Ms[m] = 0;
        }
    }
    __syncthreads();

    int wid  = tid >> 5, lane = tid & 31;
    int g    = lane >> 2, c = lane & 3;
    int q0   = wid * 32;

    uint32_t qa[2][4][4];
#pragma unroll
    for (int t = 0; t < 2; t++) {
        int r0 = q0 + t * 16 + g;
#pragma unroll
        for (int kk = 0; kk < 4; kk++) {
            int kc8 = kk * 8 + c;
            qa[t][kk][0] = Qs[r0 * ASTRIDE + kc8];
            qa[t][kk][1] = Qs[(r0 + 8) * ASTRIDE + kc8];
            qa[t][kk][2] = Qs[r0 * ASTRIDE + kc8 + 4];
            qa[t][kk][3] = Qs[(r0 + 8) * ASTRIDE + kc8 + 4];
        }
    }

    int ibq[4], cnq[4];
#pragma unroll
    for (int ri = 0; ri < 4; ri++) {
        int row = q0 + (ri >> 1) * 16 + g + (ri & 1) * 8;
        int mv = Ms[row];
        ibq[ri] = (mv & 0xffff) + 1098;
        cnq[ri] = mv >> 16;
    }

    float mrun[4] = {-1e30f, -1e30f, -1e30f, -1e30f};
    float lrun[4] = {0.f, 0.f, 0.f, 0.f};
    float o[2][4][4];
#pragma unroll
    for (int t = 0; t < 2; t++)
#pragma unroll
        for (int nb = 0; nb < 4; nb++)
#pragma unroll
            for (int j = 0; j < 4; j++) o[t][nb][j] = 0.f;

    for (int kc = 0; kc < NPAD; kc += 32) {
        int km[8];
#pragma unroll
        for (int nb = 0; nb < 4; nb++) {
#pragma unroll
            for (int e = 0; e < 2; e++)
                km[nb * 2 + e] = Ms[kc + nb * 8 + 2 * c + e];
        }

        float sa[2][4][4];
#pragma unroll
        for (int t = 0; t < 2; t++)
#pragma unroll
            for (int nb = 0; nb < 4; nb++)
#pragma unroll
                for (int j = 0; j < 4; j++) sa[t][nb][j] = 0.f;

#pragma unroll
        for (int nb = 0; nb < 4; nb++) {
            int krow = kc + nb * 8 + g;
#pragma unroll
            for (int kk = 0; kk < 4; kk++) {
                uint32_t b0 = Ks[krow * ASTRIDE + kk * 8 + c];
                uint32_t b1 = Ks[krow * ASTRIDE + kk * 8 + c + 4];
                mma8(sa[0][nb], qa[0][kk], b0, b1);
                mma8(sa[1][nb], qa[1][kk], b0, b1);
            }
        }

#pragma unroll
        for (int t = 0; t < 2; t++) {
#pragma unroll
            for (int nb = 0; nb < 4; nb++) {
#pragma unroll
                for (int sl = 0; sl < 4; sl++) {
                    int e  = sl & 1;
                    int ri = t * 2 + (sl >> 1);
                    int j  = kc + nb * 8 + 2 * c + e;
                    int kv = km[nb * 2 + e];
                    float s = sa[t][nb][sl] + Bf[ibq[ri] - (kv & 0xffff)];
                    if (cnq[ri] != (kv >> 16)) s -= 100.0f;
                    if (j >= NTOK) s = -30000.0f;
                    sa[t][nb][sl] = s;
                }
            }
        }

#pragma unroll
        for (int ri = 0; ri < 4; ri++) {
            int t = ri >> 1, rr = ri & 1;
            float mx = -3e4f;
#pragma unroll
            for (int nb = 0; nb < 4; nb++)
                mx = fmaxf(mx, fmaxf(sa[t][nb][rr * 2], sa[t][nb][rr * 2 + 1]));
            mx = fmaxf(mx, __shfl_xor_sync(0xffffffffu, mx, 1));
            mx = fmaxf(mx, __shfl_xor_sync(0xffffffffu, mx, 2));
            float mnew = fmaxf(mrun[ri], mx);
            float corr = __expf(mrun[ri] - mnew);
            mrun[ri] = mnew;
            float ls = 0.f;
#pragma unroll
            for (int nb = 0; nb < 4; nb++) {
                float p0 = __expf(sa[t][nb][rr * 2]     - mnew);
                float p1 = __expf(sa[t][nb][rr * 2 + 1] - mnew);
                sa[t][nb][rr * 2]     = p0;
                sa[t][nb][rr * 2 + 1] = p1;
                ls += p0 + p1;
            }
            ls += __shfl_xor_sync(0xffffffffu, ls, 1);
            ls += __shfl_xor_sync(0xffffffffu, ls, 2);
            lrun[ri] = lrun[ri] * corr + ls;
#pragma unroll
            for (int nb = 0; nb < 4; nb++) {
                o[t][nb][rr * 2]     *= corr;
                o[t][nb][rr * 2 + 1] *= corr;
            }
        }

        int src0 = (lane & ~3) | (c >> 1);
        int src1 = src0 + 2;
        int par  = c & 1;
#pragma unroll
        for (int kb = 0; kb < 4; kb++) {
            uint32_t ua[2][4];
#pragma unroll
            for (int t = 0; t < 2; t++) {
                float v00 = __shfl_sync(0xffffffffu, sa[t][kb][0], src0);
                float v01 = __shfl_sync(0xffffffffu, sa[t][kb][1], src0);
                float v10 = __shfl_sync(0xffffffffu, sa[t][kb][2], src0);
                float v11 = __shfl_sync(0xffffffffu, sa[t][kb][3], src0);
                float w00 = __shfl_sync(0xffffffffu, sa[t][kb][0], src1);
                float w01 = __shfl_sync(0xffffffffu, sa[t][kb][1], src1);
                float w10 = __shfl_sync(0xffffffffu, sa[t][kb][2], src1);
                float w11 = __shfl_sync(0xffffffffu, sa[t][kb][3], src1);
                ua[t][0] = f2tf32(par ? v01 : v00);
                ua[t][1] = f2tf32(par ? v11 : v10);
                ua[t][2] = f2tf32(par ? w01 : w00);
                ua[t][3] = f2tf32(par ? w11 : w10);
            }
            int vr0 = kc + kb * 8 + c;
#pragma unroll
            for (int nb = 0; nb < 4; nb++) {
                uint32_t b0 = Vs[vr0 * ASTRIDE + nb * 8 + g];
                uint32_t b1 = Vs[(vr0 + 4) * ASTRIDE + nb * 8 + g];
                mma8(o[0][nb], ua[0], b0, b1);
                mma8(o[1][nb], ua[1], b0, b1);
            }
        }
    }

    float inv[4];
#pragma unroll
    for (int ri = 0; ri < 4; ri++) inv[ri] = 1.0f / lrun[ri];

#pragma unroll
    for (int t = 0; t < 2; t++) {
        int r0 = q0 + t * 16 + g;
#pragma unroll
        for (int rr = 0; rr < 2; rr++) {
            int row = r0 + rr * 8;
            if (row < NTOK) {
                int ri = t * 2 + rr;
                float* op = g_O + ((size_t)w * NTOK + row) * CDIM + h * 32;
#pragma unroll
                for (int nb = 0; nb < 4; nb++) {
                    float2 st;
                    st.x = o[t][nb][rr * 2]     * inv[ri];
                    st.y = o[t][nb][rr * 2 + 1] * inv[ri];
                    *(float2*)(op + nb * 8 + 2 * c) = st;
                }
            }
        }
    }
}

// ---------------------------------------------------------------------------
// Launch
// ---------------------------------------------------------------------------
extern "C" void kernel_launch(void* const* d_in, const int* in_sizes, int n_in,
                              void* d_out, int out_size)
{
    const float* x      = (const float*)d_in[0];
    const float* n1g    = (const float*)d_in[1];
    const float* n1b    = (const float*)d_in[2];
    const float* qkv_w  = (const float*)d_in[3];
    const float* qkv_b  = (const float*)d_in[4];
    const float* rpb    = (const float*)d_in[5];
    const float* proj_w = (const float*)d_in[6];
    const float* proj_b = (const float*)d_in[7];
    const float* n2g    = (const float*)d_in[8];
    const float* n2b    = (const float*)d_in[9];
    const float* fc1_w  = (const float*)d_in[10];
    const float* fc1_b  = (const float*)d_in[11];
    const float* fc2_w  = (const float*)d_in[12];
    const float* fc2_b  = (const float*)d_in[13];
    float* out = (float*)d_out;

    cudaFuncSetAttribute(gemm_mma<0>, cudaFuncAttributeMaxDynamicSharedMemorySize, GEMM_SMEM);
    cudaFuncSetAttribute(gemm_mma<1>, cudaFuncAttributeMaxDynamicSharedMemorySize, GEMM_SMEM);
    cudaFuncSetAttribute(gemm_mma<2>, cudaFuncAttributeMaxDynamicSharedMemorySize, GEMM_SMEM);
    cudaFuncSetAttribute(gemm_mma<3>, cudaFuncAttributeMaxDynamicSharedMemorySize, GEMM_SMEM);
    cudaFuncSetAttribute(attn_mma, cudaFuncAttributeMaxDynamicSharedMemorySize, ATTN_SMEM);

    transpose_all<<<432, 256>>>(qkv_w, proj_w, fc1_w, fc2_w);

    ln_kernel<<<LTOK / 8, 256>>>(x, n1g, n1b);

    gemm_mma<0><<<dim3(3, 686), 256, GEMM_SMEM>>>(qkv_b, nullptr, nullptr, 96, nullptr, nullptr);

    attn_mma<<<NWIN * NHEAD, 352, ATTN_SMEM>>>(rpb);

    // proj + residual + fused LN2
    gemm_mma<1><<<dim3(1, 686), 256, GEMM_SMEM>>>(proj_b, x, nullptr, 96, n2g, n2b);

    gemm_mma<2><<<dim3(4, 686), 256, GEMM_SMEM>>>(fc1_b, nullptr, nullptr, 96, nullptr, nullptr);

    gemm_mma<3><<<dim3(1, 686), 256, GEMM_SMEM>>>(fc2_b, nullptr, out, 384, nullptr, nullptr);
}